// round 7
// baseline (speedup 1.0000x reference)
#include <cuda_runtime.h>
#include <math.h>

#define NUM_CURVES 256
#define N_CTRL 10
#define NUM_GAUSS 16384        // 256 curves * 64 points
#define IMG 256
#define TILE 16
#define NTILE (IMG / TILE)     // 16
#define NSEG 8                 // depth-range split per tile
#define GPS (NUM_GAUSS / NSEG) // 2048 gaussians per segment
#define WPG (NUM_GAUSS / 32)   // 512 mask words per tile
#define WPS (GPS / 32)         // 64 mask words per (tile,seg)
#define CUT 8.0f
#define LOG2E 1.4426950408889634f

// ---------------- device globals (scratch; zero-initialized at load) --------
__device__ float2   g_mean[NUM_GAUSS];              // depth-sorted centers
__device__ float4   g_con[NUM_CURVES];              // {A2, B2, C2, log2(alpha)}
__device__ float4   g_col[NUM_CURVES];              // {r, g, b, ry}
__device__ unsigned g_mask[NTILE * NTILE * WPG];    // per-tile survivor bitmask (idempotent OR)
__device__ float4   g_part[NSEG * IMG * IMG];       // per-segment partials {cr,cg,cb,T}
__device__ int      g_cnt[NTILE * NTILE];           // per-tile done counters (self-resetting)

__device__ __forceinline__ float sigmoidf_(float x) { return 1.0f / (1.0f + __expf(-x)); }
__device__ __forceinline__ float ftanh_(float x)    { return 1.0f - 2.0f / (__expf(2.0f * x) + 1.0f); }

// ---------------- kernel 1: sort + params + means + binning ----------------
__global__ __launch_bounds__(256)
void prep(const float* __restrict__ ctrl,
          const float* __restrict__ feat,
          const float* __restrict__ chol,
          const float* __restrict__ opac,
          const float* __restrict__ depth)
{
    __shared__ float sd[NUM_CURVES];
    __shared__ int   sord[NUM_CURVES];   // rank -> original curve
    int i = threadIdx.x;

    sd[i] = depth[i];
    __syncthreads();
    float di = sd[i];
    int rank = 0;
    #pragma unroll 16
    for (int j = 0; j < NUM_CURVES; j++) {
        float dj = sd[j];
        rank += (dj < di) || (dj == di && j < i);   // stable argsort
    }
    sord[rank] = i;
    __syncthreads();

    // this block's gaussian (sorted order)
    int g    = blockIdx.x * 256 + i;
    int slot = g >> 6;           // sorted curve slot
    int pt   = g & 63;
    int c    = sord[slot];       // original curve
    int seg  = pt >> 5;
    int s    = pt & 31;

    // covariance / conic for curve c
    float c0 = chol[3*c + 0] + 0.5f;
    float c1 = chol[3*c + 1];
    float c2 = chol[3*c + 2] + 0.5f;
    float s00 = c0*c0, s01 = c0*c1, s11 = c1*c1 + c2*c2;   // covariance
    float inv = 1.0f / (s00*s11 - s01*s01);
    float A = s11*inv, Bc = -s01*inv, C = s00*inv;          // conic
    // exact per-axis extents of {0.5 A dx^2 + B dx dy + 0.5 C dy^2 <= CUT}
    float rx = sqrtf(2.0f * CUT * s00);
    float ry = sqrtf(2.0f * CUT * s11);

    // one writer per sorted slot (pt==0); values for curve c == sord[slot]
    if (pt == 0) {
        float al = sigmoidf_(opac[c]);
        g_con[slot] = make_float4(0.5f*A*LOG2E, Bc*LOG2E, 0.5f*C*LOG2E, log2f(al));
        g_col[slot] = make_float4(sigmoidf_(feat[3*c+0]), sigmoidf_(feat[3*c+1]),
                                  sigmoidf_(feat[3*c+2]), ry);
    }

    // Bezier mean
    float t = 0.007f + (float)s * (0.986f / 31.0f);
    float u = 1.0f - t;
    float t2 = t*t, t3 = t2*t, t4 = t3*t, t5 = t4*t;
    float u2 = u*u, u3 = u2*u, u4 = u3*u, u5 = u4*u;
    float w0 = u5, w1 = 5.0f*t*u4, w2 = 10.0f*t2*u3,
          w3 = 10.0f*t3*u2, w4 = 5.0f*t4*u, w5 = t5;

    const float* cp = ctrl + c * N_CTRL * 2;
    int i0 = seg * 5;
    int i5 = (i0 + 5) % N_CTRL;
    float px = w0*cp[2*i0+0] + w1*cp[2*(i0+1)+0] + w2*cp[2*(i0+2)+0]
             + w3*cp[2*(i0+3)+0] + w4*cp[2*(i0+4)+0] + w5*cp[2*i5+0];
    float py = w0*cp[2*i0+1] + w1*cp[2*(i0+1)+1] + w2*cp[2*(i0+2)+1]
             + w3*cp[2*(i0+3)+1] + w4*cp[2*(i0+4)+1] + w5*cp[2*i5+1];

    float mx = (ftanh_(px) * 0.5f + 0.5f) * (float)IMG;
    float my = (ftanh_(py) * 0.5f + 0.5f) * (float)IMG;
    g_mean[g] = make_float2(mx, my);

    // binning with per-axis extents
    int tx0 = max(0, (int)floorf((mx - rx - 0.5f) / (float)TILE));
    int tx1 = min(NTILE - 1, (int)floorf((mx + rx - 0.5f) / (float)TILE));
    int ty0 = max(0, (int)floorf((my - ry - 0.5f) / (float)TILE));
    int ty1 = min(NTILE - 1, (int)floorf((my + ry - 0.5f) / (float)TILE));
    unsigned bit  = 1u << (g & 31);
    int      word = g >> 5;
    for (int ty = ty0; ty <= ty1; ty++)
        for (int tx = tx0; tx <= tx1; tx++)
            atomicOr(&g_mask[(ty * NTILE + tx) * WPG + word], bit);
}

// ---------------- kernel 2: tiled render (2 px/thread) + fused combine ------
__global__ __launch_bounds__(128)
void render(const float* __restrict__ bg, float* __restrict__ out)
{
    int tid  = threadIdx.x;               // 128 threads
    int lx   = tid & 15;
    int gy   = tid >> 4;                  // 0..7 (row-pair index)
    int lane = tid & 31;
    int wrp  = tid >> 5;                  // 4 warps; warp w covers rows 4w..4w+3
    int seg  = blockIdx.z;
    int tile = blockIdx.y * NTILE + blockIdx.x;

    float X0  = (float)(blockIdx.x * TILE);
    float Y0  = (float)(blockIdx.y * TILE);
    float px  = X0 + (float)lx + 0.5f;
    float py0 = Y0 + (float)(2*gy)     + 0.5f;
    float py1 = py0 + 1.0f;
    float wcy = Y0 + (float)(4*wrp) + 2.0f;   // warp's y center; halfspan 1.5

    __shared__ unsigned short slist[GPS];  // segment-local survivor ids (depth order), 4KB
    __shared__ float4 sa[128];             // {mx, my, ry, l2alpha}
    __shared__ float4 sb[128];             // {A2, B2, C2, r}
    __shared__ float2 sc[128];             // {g, b}
    __shared__ int    s_wcnt[2];
    __shared__ int    s_cnt;
    __shared__ int    s_old;

    // --- expand bitmask to local-id list (first 64 threads, order preserved) ---
    if (tid < WPS) {
        unsigned word = g_mask[tile * WPG + seg * WPS + tid];
        int cnt = __popc(word);
        int scan = cnt;
        #pragma unroll
        for (int d = 1; d < 32; d <<= 1) {
            int v = __shfl_up_sync(0xFFFFFFFFu, scan, d);
            if (lane >= d) scan += v;
        }
        if (lane == 31) s_wcnt[wrp] = scan;
        __syncthreads();
        if (tid == 0) s_cnt = s_wcnt[0] + s_wcnt[1];
        int off = scan - cnt + (wrp ? s_wcnt[0] : 0);
        int lb  = tid * 32;
        while (word) {
            int b = __ffs(word) - 1;
            word &= word - 1;
            slist[off++] = (unsigned short)(lb + b);
        }
    } else {
        __syncthreads();
    }
    __syncthreads();

    int total = s_cnt;
    float T0 = 1.0f, cr0 = 0.0f, cg0 = 0.0f, cb0 = 0.0f;
    float T1 = 1.0f, cr1 = 0.0f, cg1 = 0.0f, cb1 = 0.0f;

    for (int base = 0; base < total; base += 128) {
        int n = min(128, total - base);
        if (tid < n) {
            int g    = seg * GPS + (int)slist[base + tid];
            int slot = g >> 6;
            float2 m   = g_mean[g];
            float4 con = g_con[slot];      // A2,B2,C2,l2a
            float4 cl  = g_col[slot];      // r,g,b,ry
            sa[tid] = make_float4(m.x, m.y, cl.w, con.w);
            sb[tid] = make_float4(con.x, con.y, con.z, cl.x);
            sc[tid] = make_float2(cl.y, cl.z);
        }
        __syncthreads();

        for (int j = 0; j < n; j++) {
            float4 a4 = sa[j];                       // mx,my,ry,l2a
            // warp-strip cull: all 4 rows of this warp outside the y-extent
            if (fabsf(a4.y - wcy) > a4.z + 1.5f) continue;
            float4 b4 = sb[j];                       // A2,B2,C2,r
            float2 c2 = sc[j];                       // g,b
            float dx  = px  - a4.x;
            float dy0 = py0 - a4.y;
            float dy1 = py1 - a4.y;
            float ax  = b4.x * dx;
            float p0  = fmaf(fmaf(b4.y, dy0, ax), dx, (b4.z * dy0) * dy0);
            float p1  = fmaf(fmaf(b4.y, dy1, ax), dx, (b4.z * dy1) * dy1);
            float a0  = fminf(exp2f(a4.w - p0), 0.999f);
            float a1  = fminf(exp2f(a4.w - p1), 0.999f);
            float w0_ = a0 * T0;
            float w1_ = a1 * T1;
            cr0 = fmaf(w0_, b4.w, cr0); cg0 = fmaf(w0_, c2.x, cg0); cb0 = fmaf(w0_, c2.y, cb0);
            cr1 = fmaf(w1_, b4.w, cr1); cg1 = fmaf(w1_, c2.x, cg1); cb1 = fmaf(w1_, c2.y, cb1);
            T0 -= w0_;
            T1 -= w1_;
        }

        if (__syncthreads_and((T0 < 1e-6f) & (T1 < 1e-6f))) break;   // guards smem reuse too
    }

    int pix0 = (blockIdx.y * TILE + 2*gy) * IMG + (blockIdx.x * TILE + lx);
    int pix1 = pix0 + IMG;
    g_part[seg * (IMG*IMG) + pix0] = make_float4(cr0, cg0, cb0, T0);
    g_part[seg * (IMG*IMG) + pix1] = make_float4(cr1, cg1, cb1, T1);

    // ---- last-block-done combine ----
    __threadfence();
    __syncthreads();
    if (tid == 0) s_old = atomicAdd(&g_cnt[tile], 1);
    __syncthreads();

    if (s_old == NSEG - 1) {
        __threadfence();
        float b0 = bg[0], b1 = bg[1], b2 = bg[2];
        #pragma unroll
        for (int k = 0; k < 2; k++) {
            int pix = k ? pix1 : pix0;
            float fr = 0.0f, fg = 0.0f, fb = 0.0f, fT = 1.0f;
            #pragma unroll
            for (int s = 0; s < NSEG; s++) {
                float4 p = g_part[s * (IMG*IMG) + pix];
                fr = fmaf(fT, p.x, fr);
                fg = fmaf(fT, p.y, fg);
                fb = fmaf(fT, p.z, fb);
                fT *= p.w;
            }
            int o = pix * 3;
            out[o + 0] = fminf(fmaxf(fmaf(fT, b0, fr), 0.0f), 1.0f);
            out[o + 1] = fminf(fmaxf(fmaf(fT, b1, fg), 0.0f), 1.0f);
            out[o + 2] = fminf(fmaxf(fmaf(fT, b2, fb), 0.0f), 1.0f);
        }
        if (tid == 0) g_cnt[tile] = 0;   // self-reset for next replay
    }
}

// ---------------- launch ----------------
extern "C" void kernel_launch(void* const* d_in, const int* in_sizes, int n_in,
                              void* d_out, int out_size)
{
    const float* ctrl  = (const float*)d_in[0];   // (256,10,2)
    const float* feat  = (const float*)d_in[1];   // (256,3)
    const float* chol  = (const float*)d_in[2];   // (256,3)
    const float* opac  = (const float*)d_in[3];   // (256,1)
    const float* depth = (const float*)d_in[4];   // (256,1)
    const float* bg    = (const float*)d_in[5];   // (3,)
    float* out = (float*)d_out;                   // (256,256,3)

    prep<<<64, 256>>>(ctrl, feat, chol, opac, depth);
    render<<<dim3(NTILE, NTILE, NSEG), 128>>>(bg, out);
}

// round 8
// speedup vs baseline: 1.0921x; 1.0921x over previous
#include <cuda_runtime.h>
#include <math.h>

#define NUM_CURVES 256
#define N_CTRL 10
#define NUM_GAUSS 16384        // 256 curves * 64 points
#define IMG 256
#define TILE 16
#define NTILE (IMG / TILE)     // 16
#define NSEG 4                 // depth-range split per tile
#define GPS (NUM_GAUSS / NSEG) // 4096 gaussians per segment
#define WPG (NUM_GAUSS / 32)   // 512 mask words per tile
#define WPS (GPS / 32)         // 128 mask words per (tile,seg)
#define CUT 6.0f
#define LOG2E 1.4426950408889634f

// ---------------- device globals (scratch; zero-initialized at load) --------
__device__ float2   g_mean[NUM_GAUSS];              // depth-sorted centers
__device__ float4   g_con[NUM_CURVES];              // {A2, B2, C2, log2(alpha)}
__device__ float4   g_col[NUM_CURVES];              // {r, g, b, ry}
__device__ unsigned g_mask[NTILE * NTILE * WPG];    // per-tile survivor bitmask (idempotent OR)
__device__ float4   g_part[NSEG * IMG * IMG];       // per-segment partials {cr,cg,cb,T}
__device__ int      g_cnt[NTILE * NTILE];           // per-tile done counters (self-resetting)

__device__ __forceinline__ float sigmoidf_(float x) { return 1.0f / (1.0f + __expf(-x)); }
__device__ __forceinline__ float ftanh_(float x)    { return 1.0f - 2.0f / (__expf(2.0f * x) + 1.0f); }

// ---------------- kernel 1: sort + params + means + binning ----------------
__global__ __launch_bounds__(256)
void prep(const float* __restrict__ ctrl,
          const float* __restrict__ feat,
          const float* __restrict__ chol,
          const float* __restrict__ opac,
          const float* __restrict__ depth)
{
    __shared__ float sd[NUM_CURVES];
    __shared__ int   sord[NUM_CURVES];   // rank -> original curve
    int i = threadIdx.x;

    sd[i] = depth[i];
    __syncthreads();
    float di = sd[i];
    int rank = 0;
    #pragma unroll 16
    for (int j = 0; j < NUM_CURVES; j++) {
        float dj = sd[j];
        rank += (dj < di) || (dj == di && j < i);   // stable argsort
    }
    sord[rank] = i;
    __syncthreads();

    // this block's gaussian (sorted order)
    int g    = blockIdx.x * 256 + i;
    int slot = g >> 6;           // sorted curve slot
    int pt   = g & 63;
    int c    = sord[slot];       // original curve
    int seg  = pt >> 5;
    int s    = pt & 31;

    // covariance / conic for curve c
    float c0 = chol[3*c + 0] + 0.5f;
    float c1 = chol[3*c + 1];
    float c2 = chol[3*c + 2] + 0.5f;
    float s00 = c0*c0, s01 = c0*c1, s11 = c1*c1 + c2*c2;   // covariance
    float inv = 1.0f / (s00*s11 - s01*s01);
    float A = s11*inv, Bc = -s01*inv, C = s00*inv;          // conic
    // exact per-axis extents of {0.5 A dx^2 + B dx dy + 0.5 C dy^2 <= CUT}
    float rx = sqrtf(2.0f * CUT * s00);
    float ry = sqrtf(2.0f * CUT * s11);

    // one writer per sorted slot (pt==0); values for curve c == sord[slot]
    if (pt == 0) {
        float al = sigmoidf_(opac[c]);
        g_con[slot] = make_float4(0.5f*A*LOG2E, Bc*LOG2E, 0.5f*C*LOG2E, log2f(al));
        g_col[slot] = make_float4(sigmoidf_(feat[3*c+0]), sigmoidf_(feat[3*c+1]),
                                  sigmoidf_(feat[3*c+2]), ry);
    }

    // Bezier mean
    float t = 0.007f + (float)s * (0.986f / 31.0f);
    float u = 1.0f - t;
    float t2 = t*t, t3 = t2*t, t4 = t3*t, t5 = t4*t;
    float u2 = u*u, u3 = u2*u, u4 = u3*u, u5 = u4*u;
    float w0 = u5, w1 = 5.0f*t*u4, w2 = 10.0f*t2*u3,
          w3 = 10.0f*t3*u2, w4 = 5.0f*t4*u, w5 = t5;

    const float* cp = ctrl + c * N_CTRL * 2;
    int i0 = seg * 5;
    int i5 = (i0 + 5) % N_CTRL;
    float px = w0*cp[2*i0+0] + w1*cp[2*(i0+1)+0] + w2*cp[2*(i0+2)+0]
             + w3*cp[2*(i0+3)+0] + w4*cp[2*(i0+4)+0] + w5*cp[2*i5+0];
    float py = w0*cp[2*i0+1] + w1*cp[2*(i0+1)+1] + w2*cp[2*(i0+2)+1]
             + w3*cp[2*(i0+3)+1] + w4*cp[2*(i0+4)+1] + w5*cp[2*i5+1];

    float mx = (ftanh_(px) * 0.5f + 0.5f) * (float)IMG;
    float my = (ftanh_(py) * 0.5f + 0.5f) * (float)IMG;
    g_mean[g] = make_float2(mx, my);

    // binning with per-axis extents
    int tx0 = max(0, (int)floorf((mx - rx - 0.5f) / (float)TILE));
    int tx1 = min(NTILE - 1, (int)floorf((mx + rx - 0.5f) / (float)TILE));
    int ty0 = max(0, (int)floorf((my - ry - 0.5f) / (float)TILE));
    int ty1 = min(NTILE - 1, (int)floorf((my + ry - 0.5f) / (float)TILE));
    unsigned bit  = 1u << (g & 31);
    int      word = g >> 5;
    for (int ty = ty0; ty <= ty1; ty++)
        for (int tx = tx0; tx <= tx1; tx++)
            atomicOr(&g_mask[(ty * NTILE + tx) * WPG + word], bit);
}

// ---------------- kernel 2: tiled render (2 px/thread) + fused combine ------
__global__ __launch_bounds__(128)
void render(const float* __restrict__ bg, float* __restrict__ out)
{
    int tid  = threadIdx.x;               // 128 threads
    int lx   = tid & 15;
    int gy   = tid >> 4;                  // 0..7 (row-pair index)
    int lane = tid & 31;
    int wrp  = tid >> 5;                  // 4 warps; warp w covers rows 4w..4w+3
    int seg  = blockIdx.z;
    int tile = blockIdx.y * NTILE + blockIdx.x;

    float X0  = (float)(blockIdx.x * TILE);
    float Y0  = (float)(blockIdx.y * TILE);
    float px  = X0 + (float)lx + 0.5f;
    float py0 = Y0 + (float)(2*gy)     + 0.5f;
    float py1 = py0 + 1.0f;
    float wcy = Y0 + (float)(4*wrp) + 2.0f;   // warp's y center; halfspan 1.5

    __shared__ unsigned short slist[GPS];  // segment-local survivor ids (depth order), 8KB
    __shared__ float4 sa[128];             // {mx, my, ry, l2alpha}
    __shared__ float4 sb[128];             // {A2, B2, C2, r}
    __shared__ float2 sc[128];             // {g, b}
    __shared__ int    s_wcnt[4];
    __shared__ int    s_cnt;
    __shared__ int    s_old;

    // --- expand bitmask to local-id list (128 threads, order preserved) ---
    {
        unsigned word = g_mask[tile * WPG + seg * WPS + tid];
        int cnt = __popc(word);
        int scan = cnt;
        #pragma unroll
        for (int d = 1; d < 32; d <<= 1) {
            int v = __shfl_up_sync(0xFFFFFFFFu, scan, d);
            if (lane >= d) scan += v;
        }
        if (lane == 31) s_wcnt[wrp] = scan;
        __syncthreads();
        if (tid == 0) s_cnt = s_wcnt[0] + s_wcnt[1] + s_wcnt[2] + s_wcnt[3];
        int off = scan - cnt;
        #pragma unroll
        for (int k = 0; k < 4; k++) if (k < wrp) off += s_wcnt[k];
        int lb = tid * 32;
        while (word) {
            int b = __ffs(word) - 1;
            word &= word - 1;
            slist[off++] = (unsigned short)(lb + b);
        }
    }
    __syncthreads();

    int total = s_cnt;
    float T0 = 1.0f, cr0 = 0.0f, cg0 = 0.0f, cb0 = 0.0f;
    float T1 = 1.0f, cr1 = 0.0f, cg1 = 0.0f, cb1 = 0.0f;

    for (int base = 0; base < total; base += 128) {
        int n = min(128, total - base);
        if (tid < n) {
            int g    = seg * GPS + (int)slist[base + tid];
            int slot = g >> 6;
            float2 m   = g_mean[g];
            float4 con = g_con[slot];      // A2,B2,C2,l2a
            float4 cl  = g_col[slot];      // r,g,b,ry
            sa[tid] = make_float4(m.x, m.y, cl.w, con.w);
            sb[tid] = make_float4(con.x, con.y, con.z, cl.x);
            sc[tid] = make_float2(cl.y, cl.z);
        }
        __syncthreads();

        for (int j = 0; j < n; j++) {
            float4 a4 = sa[j];                       // mx,my,ry,l2a
            // warp-strip cull: all 4 rows of this warp outside the y-extent
            if (fabsf(a4.y - wcy) > a4.z + 1.5f) continue;
            float4 b4 = sb[j];                       // A2,B2,C2,r
            float2 c2 = sc[j];                       // g,b
            float dx  = px  - a4.x;
            float dy0 = py0 - a4.y;
            float dy1 = py1 - a4.y;
            float ax  = b4.x * dx;                   // A2*dx
            float e   = fmaf(-ax, dx, a4.w);         // l2a - A2*dx^2
            float bx  = b4.y * dx;                   // B2*dx
            float t0  = fmaf(b4.z, dy0, bx);         // C2*dy0 + B2*dx
            float t1  = fmaf(b4.z, dy1, bx);
            float g0  = fmaf(-t0, dy0, e);           // l2a - p0
            float g1  = fmaf(-t1, dy1, e);
            float a0  = fminf(exp2f(g0), 0.999f);
            float a1  = fminf(exp2f(g1), 0.999f);
            float w0_ = a0 * T0;
            float w1_ = a1 * T1;
            cr0 = fmaf(w0_, b4.w, cr0); cg0 = fmaf(w0_, c2.x, cg0); cb0 = fmaf(w0_, c2.y, cb0);
            cr1 = fmaf(w1_, b4.w, cr1); cg1 = fmaf(w1_, c2.x, cg1); cb1 = fmaf(w1_, c2.y, cb1);
            T0 -= w0_;
            T1 -= w1_;
        }

        if (__syncthreads_and((T0 < 1e-6f) & (T1 < 1e-6f))) break;   // guards smem reuse too
    }

    int pix0 = (blockIdx.y * TILE + 2*gy) * IMG + (blockIdx.x * TILE + lx);
    int pix1 = pix0 + IMG;
    g_part[seg * (IMG*IMG) + pix0] = make_float4(cr0, cg0, cb0, T0);
    g_part[seg * (IMG*IMG) + pix1] = make_float4(cr1, cg1, cb1, T1);

    // ---- last-block-done combine ----
    __threadfence();
    __syncthreads();
    if (tid == 0) s_old = atomicAdd(&g_cnt[tile], 1);
    __syncthreads();

    if (s_old == NSEG - 1) {
        __threadfence();
        float b0 = bg[0], b1 = bg[1], b2 = bg[2];
        #pragma unroll
        for (int k = 0; k < 2; k++) {
            int pix = k ? pix1 : pix0;
            float fr = 0.0f, fg = 0.0f, fb = 0.0f, fT = 1.0f;
            #pragma unroll
            for (int s = 0; s < NSEG; s++) {
                float4 p = g_part[s * (IMG*IMG) + pix];
                fr = fmaf(fT, p.x, fr);
                fg = fmaf(fT, p.y, fg);
                fb = fmaf(fT, p.z, fb);
                fT *= p.w;
            }
            int o = pix * 3;
            out[o + 0] = fminf(fmaxf(fmaf(fT, b0, fr), 0.0f), 1.0f);
            out[o + 1] = fminf(fmaxf(fmaf(fT, b1, fg), 0.0f), 1.0f);
            out[o + 2] = fminf(fmaxf(fmaf(fT, b2, fb), 0.0f), 1.0f);
        }
        if (tid == 0) g_cnt[tile] = 0;   // self-reset for next replay
    }
}

// ---------------- launch ----------------
extern "C" void kernel_launch(void* const* d_in, const int* in_sizes, int n_in,
                              void* d_out, int out_size)
{
    const float* ctrl  = (const float*)d_in[0];   // (256,10,2)
    const float* feat  = (const float*)d_in[1];   // (256,3)
    const float* chol  = (const float*)d_in[2];   // (256,3)
    const float* opac  = (const float*)d_in[3];   // (256,1)
    const float* depth = (const float*)d_in[4];   // (256,1)
    const float* bg    = (const float*)d_in[5];   // (3,)
    float* out = (float*)d_out;                   // (256,256,3)

    prep<<<64, 256>>>(ctrl, feat, chol, opac, depth);
    render<<<dim3(NTILE, NTILE, NSEG), 128>>>(bg, out);
}

// round 9
// speedup vs baseline: 1.2694x; 1.1623x over previous
#include <cuda_runtime.h>
#include <math.h>

#define NUM_CURVES 256
#define N_CTRL 10
#define NUM_GAUSS 16384        // 256 curves * 64 points
#define IMG 256
#define TILE 16
#define NTILE (IMG / TILE)     // 16
#define NSEG 4                 // depth-range split per tile
#define GPS (NUM_GAUSS / NSEG) // 4096 gaussians per segment
#define WPG (NUM_GAUSS / 32)   // 512 mask words per tile
#define WPS (GPS / 32)         // 128 mask words per (tile,seg)
#define CUT 5.0f
#define LOG2E 1.4426950408889634f

// ---------------- device globals (scratch; zero-initialized at load) --------
__device__ float2   g_mean[NUM_GAUSS];              // depth-sorted centers
__device__ float4   g_con[NUM_CURVES];              // {A2, B2, C2, log2(alpha)}
__device__ float4   g_col[NUM_CURVES];              // {r, g, b, 0}
__device__ float2   g_ext[NUM_CURVES];              // {rx, ry}
__device__ unsigned g_mask[NTILE * NTILE * WPG];    // per-tile survivor bitmask (idempotent OR)
__device__ float4   g_part[NSEG * IMG * IMG];       // per-segment partials {cr,cg,cb,T}
__device__ int      g_cnt[NTILE * NTILE];           // per-tile done counters (self-resetting)

__device__ __forceinline__ float sigmoidf_(float x) { return 1.0f / (1.0f + __expf(-x)); }
__device__ __forceinline__ float ftanh_(float x)    { return 1.0f - 2.0f / (__expf(2.0f * x) + 1.0f); }

// ---------------- kernel 1: sort + params + means + binning ----------------
__global__ __launch_bounds__(256)
void prep(const float* __restrict__ ctrl,
          const float* __restrict__ feat,
          const float* __restrict__ chol,
          const float* __restrict__ opac,
          const float* __restrict__ depth)
{
    __shared__ float sd[NUM_CURVES];
    __shared__ int   sord[NUM_CURVES];   // rank -> original curve
    int i = threadIdx.x;

    sd[i] = depth[i];
    __syncthreads();
    float di = sd[i];
    int rank = 0;
    #pragma unroll 16
    for (int j = 0; j < NUM_CURVES; j++) {
        float dj = sd[j];
        rank += (dj < di) || (dj == di && j < i);   // stable argsort
    }
    sord[rank] = i;
    __syncthreads();

    // this block's gaussian (sorted order)
    int g    = blockIdx.x * 256 + i;
    int slot = g >> 6;           // sorted curve slot
    int pt   = g & 63;
    int c    = sord[slot];       // original curve
    int seg  = pt >> 5;
    int s    = pt & 31;

    // covariance / conic for curve c
    float c0 = chol[3*c + 0] + 0.5f;
    float c1 = chol[3*c + 1];
    float c2 = chol[3*c + 2] + 0.5f;
    float s00 = c0*c0, s01 = c0*c1, s11 = c1*c1 + c2*c2;   // covariance
    float inv = 1.0f / (s00*s11 - s01*s01);
    float A = s11*inv, Bc = -s01*inv, C = s00*inv;          // conic
    // exact per-axis extents of {0.5 A dx^2 + B dx dy + 0.5 C dy^2 <= CUT}
    float rx = sqrtf(2.0f * CUT * s00);
    float ry = sqrtf(2.0f * CUT * s11);

    // one writer per sorted slot (pt==0); values for curve c == sord[slot]
    if (pt == 0) {
        float al = sigmoidf_(opac[c]);
        g_con[slot] = make_float4(0.5f*A*LOG2E, Bc*LOG2E, 0.5f*C*LOG2E, log2f(al));
        g_col[slot] = make_float4(sigmoidf_(feat[3*c+0]), sigmoidf_(feat[3*c+1]),
                                  sigmoidf_(feat[3*c+2]), 0.0f);
        g_ext[slot] = make_float2(rx, ry);
    }

    // Bezier mean
    float t = 0.007f + (float)s * (0.986f / 31.0f);
    float u = 1.0f - t;
    float t2 = t*t, t3 = t2*t, t4 = t3*t, t5 = t4*t;
    float u2 = u*u, u3 = u2*u, u4 = u3*u, u5 = u4*u;
    float w0 = u5, w1 = 5.0f*t*u4, w2 = 10.0f*t2*u3,
          w3 = 10.0f*t3*u2, w4 = 5.0f*t4*u, w5 = t5;

    const float* cp = ctrl + c * N_CTRL * 2;
    int i0 = seg * 5;
    int i5 = (i0 + 5) % N_CTRL;
    float px = w0*cp[2*i0+0] + w1*cp[2*(i0+1)+0] + w2*cp[2*(i0+2)+0]
             + w3*cp[2*(i0+3)+0] + w4*cp[2*(i0+4)+0] + w5*cp[2*i5+0];
    float py = w0*cp[2*i0+1] + w1*cp[2*(i0+1)+1] + w2*cp[2*(i0+2)+1]
             + w3*cp[2*(i0+3)+1] + w4*cp[2*(i0+4)+1] + w5*cp[2*i5+1];

    float mx = (ftanh_(px) * 0.5f + 0.5f) * (float)IMG;
    float my = (ftanh_(py) * 0.5f + 0.5f) * (float)IMG;
    g_mean[g] = make_float2(mx, my);

    // binning with per-axis extents
    int tx0 = max(0, (int)floorf((mx - rx - 0.5f) / (float)TILE));
    int tx1 = min(NTILE - 1, (int)floorf((mx + rx - 0.5f) / (float)TILE));
    int ty0 = max(0, (int)floorf((my - ry - 0.5f) / (float)TILE));
    int ty1 = min(NTILE - 1, (int)floorf((my + ry - 0.5f) / (float)TILE));
    unsigned bit  = 1u << (g & 31);
    int      word = g >> 5;
    for (int ty = ty0; ty <= ty1; ty++)
        for (int tx = tx0; tx <= tx1; tx++)
            atomicOr(&g_mask[(ty * NTILE + tx) * WPG + word], bit);
}

// ---------------- kernel 2: quadrant-warp render + fused combine ------------
__global__ __launch_bounds__(128)
void render(const float* __restrict__ bg, float* __restrict__ out)
{
    int tid  = threadIdx.x;               // 128 threads
    int lane = tid & 31;
    int wrp  = tid >> 5;                  // warp -> 8x8 quadrant
    int qx   = (wrp & 1) * 8;
    int qy   = (wrp >> 1) * 8;
    int lx   = lane & 7;                  // 0..7 within quadrant
    int gy   = lane >> 3;                 // 0..3 row-pair
    int seg  = blockIdx.z;
    int tile = blockIdx.y * NTILE + blockIdx.x;

    float X0  = (float)(blockIdx.x * TILE);
    float Y0  = (float)(blockIdx.y * TILE);
    float px  = X0 + (float)(qx + lx) + 0.5f;
    float py0 = Y0 + (float)(qy + 2*gy) + 0.5f;
    float py1 = py0 + 1.0f;
    float qcx = X0 + (float)qx + 4.0f;    // quadrant center; halfspan 3.5
    float qcy = Y0 + (float)qy + 4.0f;

    __shared__ unsigned short slist[GPS];        // segment-local survivor ids, 8KB
    __shared__ float4 scul[128];                 // {mx, my, rx, ry}
    __shared__ float4 sb[128];                   // {A2, B2, C2, l2a}
    __shared__ float4 sc[128];                   // {r, g, b, -}
    __shared__ unsigned char widx[4 * 128];      // per-warp compacted chunk indices
    __shared__ int    s_wcnt[4];
    __shared__ int    s_cnt;
    __shared__ int    s_old;

    // --- expand bitmask to local-id list (128 threads, order preserved) ---
    {
        unsigned word = g_mask[tile * WPG + seg * WPS + tid];
        int cnt = __popc(word);
        int scan = cnt;
        #pragma unroll
        for (int d = 1; d < 32; d <<= 1) {
            int v = __shfl_up_sync(0xFFFFFFFFu, scan, d);
            if (lane >= d) scan += v;
        }
        if (lane == 31) s_wcnt[wrp] = scan;
        __syncthreads();
        if (tid == 0) s_cnt = s_wcnt[0] + s_wcnt[1] + s_wcnt[2] + s_wcnt[3];
        int off = scan - cnt;
        #pragma unroll
        for (int k = 0; k < 4; k++) if (k < wrp) off += s_wcnt[k];
        int lb = tid * 32;
        while (word) {
            int b = __ffs(word) - 1;
            word &= word - 1;
            slist[off++] = (unsigned short)(lb + b);
        }
    }
    __syncthreads();

    int total = s_cnt;
    float T0 = 1.0f, cr0 = 0.0f, cg0 = 0.0f, cb0 = 0.0f;
    float T1 = 1.0f, cr1 = 0.0f, cg1 = 0.0f, cb1 = 0.0f;

    for (int base = 0; base < total; base += 128) {
        int n = min(128, total - base);
        if (tid < n) {
            int g    = seg * GPS + (int)slist[base + tid];
            int slot = g >> 6;
            float2 m  = g_mean[g];
            float2 ex = g_ext[slot];
            scul[tid] = make_float4(m.x, m.y, ex.x, ex.y);
            sb[tid]   = g_con[slot];
            sc[tid]   = g_col[slot];
        }
        __syncthreads();

        bool dead = (T0 < 1e-6f) && (T1 < 1e-6f);
        if (!__all_sync(0xFFFFFFFFu, dead)) {
            // --- per-warp 2D-cull compaction (order-preserving) ---
            int wn = 0;
            #pragma unroll
            for (int k = 0; k < 4; k++) {
                int idx = k * 32 + lane;
                bool ok = false;
                if (idx < n) {
                    float4 cu = scul[idx];
                    ok = (fabsf(cu.x - qcx) <= cu.z + 3.5f) &&
                         (fabsf(cu.y - qcy) <= cu.w + 3.5f);
                }
                unsigned mk = __ballot_sync(0xFFFFFFFFu, ok);
                if (ok)
                    widx[wrp * 128 + wn + __popc(mk & ((1u << lane) - 1u))] =
                        (unsigned char)idx;
                wn += __popc(mk);
            }
            __syncwarp();

            for (int j = 0; j < wn; j++) {
                int   idx = (int)widx[wrp * 128 + j];
                float4 cu = scul[idx];                   // mx,my (rx,ry unused here)
                float4 b4 = sb[idx];                     // A2,B2,C2,l2a
                float4 c4 = sc[idx];                     // r,g,b
                float dx  = px  - cu.x;
                float dy0 = py0 - cu.y;
                float dy1 = py1 - cu.y;
                float e   = fmaf(-b4.x * dx, dx, b4.w);  // l2a - A2*dx^2
                float bx  = b4.y * dx;                   // B2*dx
                float t0  = fmaf(b4.z, dy0, bx);
                float t1  = fmaf(b4.z, dy1, bx);
                float g0  = fmaf(-t0, dy0, e);
                float g1  = fmaf(-t1, dy1, e);
                float a0  = fminf(exp2f(g0), 0.999f);
                float a1  = fminf(exp2f(g1), 0.999f);
                float w0_ = a0 * T0;
                float w1_ = a1 * T1;
                cr0 = fmaf(w0_, c4.x, cr0); cg0 = fmaf(w0_, c4.y, cg0); cb0 = fmaf(w0_, c4.z, cb0);
                cr1 = fmaf(w1_, c4.x, cr1); cg1 = fmaf(w1_, c4.y, cg1); cb1 = fmaf(w1_, c4.z, cb1);
                T0 -= w0_;
                T1 -= w1_;
            }
        }

        if (__syncthreads_and((T0 < 1e-6f) & (T1 < 1e-6f))) break;  // guards smem reuse
    }

    int pix0 = (blockIdx.y * TILE + qy + 2*gy) * IMG + (blockIdx.x * TILE + qx + lx);
    int pix1 = pix0 + IMG;
    g_part[seg * (IMG*IMG) + pix0] = make_float4(cr0, cg0, cb0, T0);
    g_part[seg * (IMG*IMG) + pix1] = make_float4(cr1, cg1, cb1, T1);

    // ---- last-block-done combine ----
    __threadfence();
    __syncthreads();
    if (tid == 0) s_old = atomicAdd(&g_cnt[tile], 1);
    __syncthreads();

    if (s_old == NSEG - 1) {
        __threadfence();
        float b0 = bg[0], b1 = bg[1], b2 = bg[2];
        #pragma unroll
        for (int k = 0; k < 2; k++) {
            int pix = k ? pix1 : pix0;
            float fr = 0.0f, fg = 0.0f, fb = 0.0f, fT = 1.0f;
            #pragma unroll
            for (int s = 0; s < NSEG; s++) {
                float4 p = g_part[s * (IMG*IMG) + pix];
                fr = fmaf(fT, p.x, fr);
                fg = fmaf(fT, p.y, fg);
                fb = fmaf(fT, p.z, fb);
                fT *= p.w;
            }
            int o = pix * 3;
            out[o + 0] = fminf(fmaxf(fmaf(fT, b0, fr), 0.0f), 1.0f);
            out[o + 1] = fminf(fmaxf(fmaf(fT, b1, fg), 0.0f), 1.0f);
            out[o + 2] = fminf(fmaxf(fmaf(fT, b2, fb), 0.0f), 1.0f);
        }
        if (tid == 0) g_cnt[tile] = 0;   // self-reset for next replay
    }
}

// ---------------- launch ----------------
extern "C" void kernel_launch(void* const* d_in, const int* in_sizes, int n_in,
                              void* d_out, int out_size)
{
    const float* ctrl  = (const float*)d_in[0];   // (256,10,2)
    const float* feat  = (const float*)d_in[1];   // (256,3)
    const float* chol  = (const float*)d_in[2];   // (256,3)
    const float* opac  = (const float*)d_in[3];   // (256,1)
    const float* depth = (const float*)d_in[4];   // (256,1)
    const float* bg    = (const float*)d_in[5];   // (3,)
    float* out = (float*)d_out;                   // (256,256,3)

    prep<<<64, 256>>>(ctrl, feat, chol, opac, depth);
    render<<<dim3(NTILE, NTILE, NSEG), 128>>>(bg, out);
}